// round 6
// baseline (speedup 1.0000x reference)
#include <cuda_runtime.h>
#include <cuda_bf16.h>
#include <math.h>

#define G 128
#define NODES 256
#define DFEAT 128
#define KB 16
#define PITCHC 132           // fp32 pitch for kC smem

// H bf16 pitch (elements): 136 -> 272B row stride, conflict-free ldmatrix
#define PH 136

// smem byte offsets for fused kernel
#define OFF_H    0
#define OFF_D    69632                   // 256*136*2 ; D tiles: 136*512B = 69632
#define OFF_SQ   (OFF_D + 69632)        // 139264: float[256]
#define OFF_RED  (OFF_SQ + 1024)        // float[16]
#define OFF_HIST (OFF_RED + 64)         // float[256 + 18]
#define SMEM_AB  (OFF_HIST + 4 * (256 + 18) + 16)

// factorized-exp constants: sigma = 3/16, alpha = 0.5/sigma^2 = 128/9
#define C_C1      0.32052948f            // exp(-256/225)
#define C_C3      0.03293272f            // c^3
#define C_C4      0.01055548f            // c^4
// log2e-folded: w0 = exp2(K_W*x^2), r0 = exp2(K_L*x + K_O)
#define K_W     (-20.5183296f)           // -(128/9)*log2(e)
#define K_L       8.2073318f             // (256/45)*log2(e)
#define K_O      (-0.82073318f)          // -(128/225)*log2(e)

__device__ float g_sig[256 * KB];
__device__ float g_ntx[32];
__device__ int   g_cnt;                  // zero-init; reset by consumer

// slot -> tile code (ti<<4)|tj. Slots 0..15 = diagonal tiles, 16..135 = upper off-diag.
__constant__ unsigned char c_slot[136] = {
    0x00,0x11,0x22,0x33,0x44,0x55,0x66,0x77,0x88,0x99,0xAA,0xBB,0xCC,0xDD,0xEE,0xFF,
    0x01,0x02,0x03,0x04,0x05,0x06,0x07,0x08,0x09,0x0A,0x0B,0x0C,0x0D,0x0E,0x0F,
    0x12,0x13,0x14,0x15,0x16,0x17,0x18,0x19,0x1A,0x1B,0x1C,0x1D,0x1E,0x1F,
    0x23,0x24,0x25,0x26,0x27,0x28,0x29,0x2A,0x2B,0x2C,0x2D,0x2E,0x2F,
    0x34,0x35,0x36,0x37,0x38,0x39,0x3A,0x3B,0x3C,0x3D,0x3E,0x3F,
    0x45,0x46,0x47,0x48,0x49,0x4A,0x4B,0x4C,0x4D,0x4E,0x4F,
    0x56,0x57,0x58,0x59,0x5A,0x5B,0x5C,0x5D,0x5E,0x5F,
    0x67,0x68,0x69,0x6A,0x6B,0x6C,0x6D,0x6E,0x6F,
    0x78,0x79,0x7A,0x7B,0x7C,0x7D,0x7E,0x7F,
    0x89,0x8A,0x8B,0x8C,0x8D,0x8E,0x8F,
    0x9A,0x9B,0x9C,0x9D,0x9E,0x9F,
    0xAB,0xAC,0xAD,0xAE,0xAF,
    0xBC,0xBD,0xBE,0xBF,
    0xCD,0xCE,0xCF,
    0xDE,0xDF,
    0xEF
};

__device__ __forceinline__ float warpSum(float v) {
#pragma unroll
    for (int o = 16; o > 0; o >>= 1) v += __shfl_down_sync(0xffffffffu, v, o);
    return v;
}

__device__ __forceinline__ float ex2a(float x) {
    float r;
    asm("ex2.approx.f32 %0, %1;" : "=f"(r) : "f"(x));
    return r;
}
__device__ __forceinline__ float sqrta(float x) {
    float r;
    asm("sqrt.approx.f32 %0, %1;" : "=f"(r) : "f"(x));
    return r;
}

// ---- packed f32x2 helpers (Blackwell) ----
__device__ __forceinline__ unsigned long long pk2(float a, float b) {
    unsigned long long r;
    asm("mov.b64 %0, {%1, %2};" : "=l"(r) : "f"(a), "f"(b));
    return r;
}
__device__ __forceinline__ void upk2(unsigned long long v, float& a, float& b) {
    asm("mov.b64 {%0, %1}, %2;" : "=f"(a), "=f"(b) : "l"(v));
}
__device__ __forceinline__ unsigned long long mul2(unsigned long long a, unsigned long long b) {
    unsigned long long r;
    asm("mul.rn.f32x2 %0, %1, %2;" : "=l"(r) : "l"(a), "l"(b));
    return r;
}
__device__ __forceinline__ unsigned long long add2(unsigned long long a, unsigned long long b) {
    unsigned long long r;
    asm("add.rn.f32x2 %0, %1, %2;" : "=l"(r) : "l"(a), "l"(b));
    return r;
}

__device__ __forceinline__ void ldsm_x4(unsigned smaddr, unsigned& r0, unsigned& r1,
                                        unsigned& r2, unsigned& r3) {
    asm volatile("ldmatrix.sync.aligned.m8n8.x4.shared.b16 {%0,%1,%2,%3}, [%4];"
                 : "=r"(r0), "=r"(r1), "=r"(r2), "=r"(r3) : "r"(smaddr));
}
__device__ __forceinline__ void mma_bf16(float& c0, float& c1, float& c2, float& c3,
                                         unsigned a0, unsigned a1, unsigned a2, unsigned a3,
                                         unsigned b0, unsigned b1) {
    asm volatile("mma.sync.aligned.m16n8k16.row.col.f32.bf16.bf16.f32 "
                 "{%0,%1,%2,%3}, {%4,%5,%6,%7}, {%8,%9}, {%0,%1,%2,%3};"
                 : "+f"(c0), "+f"(c1), "+f"(c2), "+f"(c3)
                 : "r"(a0), "r"(a1), "r"(a2), "r"(a3), "r"(b0), "r"(b1));
}

// weighted bins-in-lanes accumulate of one pair
__device__ __forceinline__ void accumW(float d, float invm, float wt,
                                       unsigned long long* Hc, unsigned long long C4p) {
    float x = fminf(d * invm, 2.46f);
    float w0 = wt * ex2a(K_W * x * x);
    float r0 = ex2a(fmaf(K_L, x, K_O));
    float w1 = w0 * r0;
    float r2 = r0 * r0;
    unsigned long long W = pk2(w0, w1);
    unsigned long long M = pk2(r2 * C_C1, r2 * C_C3);
    Hc[0] = add2(Hc[0], W);
#pragma unroll
    for (int p = 1; p < 8; p++) {
        W = mul2(W, M);
        M = mul2(M, C4p);
        Hc[p] = add2(Hc[p], W);
    }
}

__device__ __forceinline__ float wgt_diag(int el) {
    int lr = el >> 4, lc = el & 15;
    return (lc > lr) ? 2.f : ((lc == lr) ? 1.f : 0.f);
}

// ---------------------------------------------------------------------------
// Fused kernel: per graph-view (256 blocks x 512 threads):
//   1. load H -> bf16 smem
//   2. upper-triangle Gram tiles via mma.sync; D -> tile-packed bf16 smem;
//      weighted sum(D)
//   3. factorized-exp soft histogram, weight-fused, 2 accumulator banks
// ---------------------------------------------------------------------------
__global__ void __launch_bounds__(512, 1)
kAB(const float* __restrict__ H1, const float* __restrict__ H2) {
    extern __shared__ char sm[];
    __nv_bfloat16* sH = (__nv_bfloat16*)(sm + OFF_H);
    float* sSq   = (float*)(sm + OFF_SQ);
    float* sRed  = (float*)(sm + OFF_RED);
    float* sHist = (float*)(sm + OFF_HIST);

    const unsigned smBase = (unsigned)__cvta_generic_to_shared(sm);
    const unsigned sHb = smBase + OFF_H;

    int gv  = blockIdx.x;
    int tid = threadIdx.x;
    int w = tid >> 5, lane = tid & 31;
    const float* Hg = (gv < G) ? (H1 + (size_t)gv * NODES * DFEAT)
                               : (H2 + (size_t)(gv - G) * NODES * DFEAT);

    // ---- load H, convert to bf16 (pitched) ----
    for (int t = tid; t < NODES * (DFEAT / 4); t += 512) {
        int row = t >> 5, c4 = t & 31;
        float4 v = ((const float4*)Hg)[(size_t)row * (DFEAT / 4) + c4];
        __nv_bfloat162 b01 = __floats2bfloat162_rn(v.x, v.y);
        __nv_bfloat162 b23 = __floats2bfloat162_rn(v.z, v.w);
        uint2 u;
        u.x = *(unsigned*)&b01;
        u.y = *(unsigned*)&b23;
        *(uint2*)(sm + OFF_H + (row * PH + c4 * 4) * 2) = u;
    }
    __syncthreads();

    // ---- row norms from bf16 values ----
    if (tid < NODES) {
        const __nv_bfloat162* r = (const __nv_bfloat162*)(sH + tid * PH);
        float s = 0.f;
#pragma unroll 8
        for (int k = 0; k < DFEAT / 2; k++) {
            float2 f = __bfloat1622float2(r[k]);
            s = fmaf(f.x, f.x, s);
            s = fmaf(f.y, f.y, s);
        }
        sSq[tid] = s;
    }
    __syncthreads();

    // ---- Gram over upper-triangle tiles; warp w handles slots w, w+16, ... ----
    int lrow = lane & 15;
    int lcol8 = (lane >> 4) << 3;
    int gq = lane >> 2;        // 0..7
    int tq = lane & 3;         // 0..3
    float dsum = 0.f;

    for (int s = w; s < 136; s += 16) {
        int tt = c_slot[s];
        int i0 = (tt >> 4) * 16, j0 = (tt & 15) * 16;
        bool isDiag = (s < 16);

        unsigned a[8][4];
#pragma unroll
        for (int kc = 0; kc < 8; kc++) {
            unsigned ad = sHb + 2u * ((i0 + lrow) * PH + kc * 16 + lcol8);
            ldsm_x4(ad, a[kc][0], a[kc][1], a[kc][2], a[kc][3]);
        }

        float c0[4] = {0.f, 0.f, 0.f, 0.f};
        float c1[4] = {0.f, 0.f, 0.f, 0.f};
#pragma unroll
        for (int kc = 0; kc < 8; kc++) {
            unsigned bd = sHb + 2u * ((j0 + lrow) * PH + kc * 16 + lcol8);
            unsigned b0, b1, b2, b3;
            ldsm_x4(bd, b0, b1, b2, b3);
            mma_bf16(c0[0], c0[1], c0[2], c0[3], a[kc][0], a[kc][1], a[kc][2], a[kc][3], b0, b2);
            mma_bf16(c1[0], c1[1], c1[2], c1[3], a[kc][0], a[kc][1], a[kc][2], a[kc][3], b1, b3);
        }

#pragma unroll
        for (int t2 = 0; t2 < 2; t2++) {
            const float* cc = t2 ? c1 : c0;
            int lc = t2 * 8 + 2 * tq;
            int jc = j0 + lc;
            float sqj0 = sSq[jc], sqj1 = sSq[jc + 1];
#pragma unroll
            for (int rh = 0; rh < 2; rh++) {
                int lr = gq + rh * 8;
                int r = i0 + lr;
                float sqi = sSq[r];
                float da = sqrta(fmaxf(fmaf(-2.f, cc[rh * 2 + 0], sqi + sqj0), 0.f) + 1e-12f);
                float db = sqrta(fmaxf(fmaf(-2.f, cc[rh * 2 + 1], sqi + sqj1), 0.f) + 1e-12f);
                if (!isDiag) {
                    dsum += 2.f * (da + db);
                } else {
                    float wa = (lc > lr) ? 2.f : ((lc == lr) ? 1.f : 0.f);
                    float wb = (lc + 1 > lr) ? 2.f : ((lc + 1 == lr) ? 1.f : 0.f);
                    dsum = fmaf(wa, da, dsum);
                    dsum = fmaf(wb, db, dsum);
                }
                __nv_bfloat162 dd = __floats2bfloat162_rn(da, db);
                *(unsigned*)(sm + OFF_D + s * 512 + lr * 32 + lc * 2) = *(unsigned*)&dd;
            }
        }
    }

    dsum = warpSum(dsum);
    if (lane == 0) sRed[w] = dsum;
    __syncthreads();
    if (tid == 0) {
        float tot = 0.f;
#pragma unroll
        for (int i = 0; i < 16; i++) tot += sRed[i];
        float mean = tot * (1.0f / 65536.0f);
        sHist[256 + 16] = 1.0f / (mean + 1e-8f);
    }
    __syncthreads();
    float invm = sHist[256 + 16];

    // ---- histogram: thread t owns contiguous elements [t*68, t*68+68) ----
    unsigned long long HA[8], HB[8];
#pragma unroll
    for (int p = 0; p < 8; p++) { HA[p] = pk2(0.f, 0.f); HB[p] = pk2(0.f, 0.f); }
    const unsigned long long C4p = pk2(C_C4, C_C4);

    {
        int base = tid * 68;                      // element index
        const char* Dp = sm + OFF_D + base * 2;
        if (base >= 4096) {
            // pure off-diagonal region: weight 2 everywhere
#pragma unroll 4
            for (int it = 0; it < 17; it++) {
                uint2 v = *(const uint2*)(Dp + it * 8);
                float f0 = __uint_as_float(v.x << 16);
                float f1 = __uint_as_float(v.x & 0xffff0000u);
                float f2 = __uint_as_float(v.y << 16);
                float f3 = __uint_as_float(v.y & 0xffff0000u);
                accumW(f0, invm, 2.f, HA, C4p);
                accumW(f1, invm, 2.f, HB, C4p);
                accumW(f2, invm, 2.f, HA, C4p);
                accumW(f3, invm, 2.f, HB, C4p);
            }
        } else {
            // diagonal-tile region (or boundary): per-element weights
#pragma unroll 4
            for (int it = 0; it < 17; it++) {
                uint2 v = *(const uint2*)(Dp + it * 8);
                int e = base + it * 4;
                float f0 = __uint_as_float(v.x << 16);
                float f1 = __uint_as_float(v.x & 0xffff0000u);
                float f2 = __uint_as_float(v.y << 16);
                float f3 = __uint_as_float(v.y & 0xffff0000u);
                float w0 = (e + 0 >= 4096) ? 2.f : wgt_diag((e + 0) & 255);
                float w1 = (e + 1 >= 4096) ? 2.f : wgt_diag((e + 1) & 255);
                float w2 = (e + 2 >= 4096) ? 2.f : wgt_diag((e + 2) & 255);
                float w3 = (e + 3 >= 4096) ? 2.f : wgt_diag((e + 3) & 255);
                accumW(f0, invm, w0, HA, C4p);
                accumW(f1, invm, w1, HB, C4p);
                accumW(f2, invm, w2, HA, C4p);
                accumW(f3, invm, w3, HB, C4p);
            }
        }
    }

    float hl[16];
#pragma unroll
    for (int p = 0; p < 8; p++) {
        float a0, a1, b0, b1;
        upk2(HA[p], a0, a1);
        upk2(HB[p], b0, b1);
        hl[2 * p] = a0 + b0;
        hl[2 * p + 1] = a1 + b1;
    }

#pragma unroll
    for (int k = 0; k < 16; k++) {
        float v = warpSum(hl[k]);
        if (lane == 0) sHist[w * 16 + k] = v;
    }
    __syncthreads();
    if (tid < 16) {
        float s = 0.f;
#pragma unroll
        for (int ww = 0; ww < 16; ww++) s += sHist[ww * 16 + tid];
        sHist[256 + tid] = s;
    }
    __syncthreads();
    if (tid == 0) {
        float S = 0.f;
#pragma unroll
        for (int k = 0; k < 16; k++) S += sHist[256 + k];
        sHist[256 + 17] = 1.0f / (S + 1e-8f);
    }
    __syncthreads();
    if (tid < 16) g_sig[gv * KB + tid] = sHist[256 + tid] * sHist[256 + 17];
}

// ---------------------------------------------------------------------------
// NT-Xent (32 blocks x 8 rows) with the final combine folded into the last
// block to finish (atomic ticket) — removes the kD launch.
// ---------------------------------------------------------------------------
__global__ void __launch_bounds__(256, 1)
kC(const float* __restrict__ z1, const float* __restrict__ z2, float* out) {
    extern __shared__ float smf[];
    float* zn = smf;
    float* sRed = smf + 256 * PITCHC;

    int tid = threadIdx.x;
    for (int t = tid; t < 2 * G * DFEAT; t += 256) {
        int row = t >> 7, k = t & 127;
        float v = (row < G) ? z1[t] : z2[t - G * DFEAT];
        zn[row * PITCHC + k] = v;
    }
    __syncthreads();
    {
        int row = tid;
        float* r = zn + row * PITCHC;
        float s = 0.f;
#pragma unroll 8
        for (int k = 0; k < DFEAT; k++) s += r[k] * r[k];
        float inv = 1.0f / (sqrtf(s) + 1e-8f);
#pragma unroll 8
        for (int k = 0; k < DFEAT; k++) r[k] *= inv;
    }
    __syncthreads();

    int w = tid >> 5, lane = tid & 31;
    int i = blockIdx.x * 8 + w;
    int label = (i < G) ? i + G : i - G;
    const float* zi = zn + i * PITCHC;

    float sims[8];
#pragma unroll
    for (int s = 0; s < 8; s++) {
        int j = lane + 32 * s;
        const float* zj = zn + j * PITCHC;
        float acc = 0.f;
        for (int k = 0; k < DFEAT; k += 4) {
            float4 a = *(const float4*)(zi + k);
            float4 b = *(const float4*)(zj + k);
            acc = fmaf(a.x, b.x, acc);
            acc = fmaf(a.y, b.y, acc);
            acc = fmaf(a.z, b.z, acc);
            acc = fmaf(a.w, b.w, acc);
        }
        float sim = acc * 2.0f;
        if (j == i) sim = -1e9f;
        sims[s] = sim;
    }

    float m = -1e30f, slab = 0.f;
#pragma unroll
    for (int s = 0; s < 8; s++) {
        m = fmaxf(m, sims[s]);
        if (lane + 32 * s == label) slab = sims[s];
    }
#pragma unroll
    for (int o = 16; o > 0; o >>= 1)
        m = fmaxf(m, __shfl_xor_sync(0xffffffffu, m, o));

    float se = 0.f;
#pragma unroll
    for (int s = 0; s < 8; s++) se += __expf(sims[s] - m);
    se = warpSum(se);
    slab = warpSum(slab);

    if (lane == 0) sRed[w] = (m + logf(se)) - slab;
    __syncthreads();
    if (tid == 0) {
        float t = 0.f;
        for (int s = 0; s < 8; s++) t += sRed[s];
        g_ntx[blockIdx.x] = t;
    }

    // ---- last block to finish computes the final scalar ----
    __threadfence();
    __shared__ int sLast;
    if (tid == 0) sLast = (atomicAdd(&g_cnt, 1) == 31) ? 1 : 0;
    __syncthreads();
    if (sLast) {
        if (tid == 0) g_cnt = 0;     // reset for next replay
        __threadfence();
        __shared__ float sR2[4];
        float t2 = 0.f;
        if (tid < 128) {
            const float* a = g_sig + tid * KB;
            const float* b = g_sig + (G + tid) * KB;
#pragma unroll
            for (int k = 0; k < KB; k++) {
                float d = a[k] - b[k];
                t2 += d * d;
            }
            t2 *= (1.0f / KB);
        }
        t2 = warpSum(t2);
        if (lane == 0 && w < 4) sR2[w] = t2;
        __syncthreads();
        float ntx = 0.f;
        if (tid < 32) {
            ntx = g_ntx[tid];
            ntx = warpSum(ntx);
        }
        if (tid == 0) {
            float topo = (sR2[0] + sR2[1] + sR2[2] + sR2[3]) * (1.0f / G);
            out[0] = 0.1f * (topo + ntx * (1.0f / 256.0f));
        }
    }
}

// ---------------------------------------------------------------------------
extern "C" void kernel_launch(void* const* d_in, const int* in_sizes, int n_in,
                              void* d_out, int out_size) {
    const float* H1 = (const float*)d_in[0];
    const float* H2 = (const float*)d_in[2];
    const float* z1 = (const float*)d_in[4];
    const float* z2 = (const float*)d_in[5];

    size_t smAB = SMEM_AB;
    size_t smC = (size_t)(256 * PITCHC + 32) * sizeof(float);
    cudaFuncSetAttribute(kAB, cudaFuncAttributeMaxDynamicSharedMemorySize, (int)smAB);
    cudaFuncSetAttribute(kC, cudaFuncAttributeMaxDynamicSharedMemorySize, (int)smC);

    kAB<<<256, 512, smAB>>>(H1, H2);
    kC<<<32, 256, smC>>>(z1, z2, (float*)d_out);
}

// round 8
// speedup vs baseline: 1.2494x; 1.2494x over previous
#include <cuda_runtime.h>
#include <cuda_bf16.h>
#include <math.h>

#define G 128
#define NODES 256
#define DFEAT 128
#define KB 16

// H bf16 pitch (elements)
#define PH 136
// NT-Xent z pitch in u32 words (odd -> conflict-free LDS.32)
#define PZW 65

// smem byte offsets
#define OFF_H    0
#define OFF_D    69632                  // u8 D tiles: 136*256 = 34816
#define OFF_SQ   104448                 // float[256]
#define OFF_RED  105472                 // float[16]
#define OFF_HIST 105536                 // float[256]
#define OFF_MISC 106560                 // float[8]
#define SMEM_T   106624

// factorized-exp constants: sigma = 3/16
#define C_C1      0.32052948f           // exp(-256/225)
#define C_C3      0.03293272f           // c^3
#define C_C4      0.01055548f           // c^4
#define K_W     (-20.5183296f)          // -(128/9)*log2(e)
#define K_L       8.2073318f            // (256/45)*log2(e)
#define K_O      (-0.82073318f)         // -(128/225)*log2(e)

__device__ float g_sig[256 * KB];
__device__ float g_ntx[16];
__device__ int   g_cnt;                 // zero-init; reset by final block

// slot -> tile code (ti<<4)|tj. Slots 0..15 diagonal, 16..135 upper off-diag.
__constant__ unsigned char c_slot[136] = {
    0x00,0x11,0x22,0x33,0x44,0x55,0x66,0x77,0x88,0x99,0xAA,0xBB,0xCC,0xDD,0xEE,0xFF,
    0x01,0x02,0x03,0x04,0x05,0x06,0x07,0x08,0x09,0x0A,0x0B,0x0C,0x0D,0x0E,0x0F,
    0x12,0x13,0x14,0x15,0x16,0x17,0x18,0x19,0x1A,0x1B,0x1C,0x1D,0x1E,0x1F,
    0x23,0x24,0x25,0x26,0x27,0x28,0x29,0x2A,0x2B,0x2C,0x2D,0x2E,0x2F,
    0x34,0x35,0x36,0x37,0x38,0x39,0x3A,0x3B,0x3C,0x3D,0x3E,0x3F,
    0x45,0x46,0x47,0x48,0x49,0x4A,0x4B,0x4C,0x4D,0x4E,0x4F,
    0x56,0x57,0x58,0x59,0x5A,0x5B,0x5C,0x5D,0x5E,0x5F,
    0x67,0x68,0x69,0x6A,0x6B,0x6C,0x6D,0x6E,0x6F,
    0x78,0x79,0x7A,0x7B,0x7C,0x7D,0x7E,0x7F,
    0x89,0x8A,0x8B,0x8C,0x8D,0x8E,0x8F,
    0x9A,0x9B,0x9C,0x9D,0x9E,0x9F,
    0xAB,0xAC,0xAD,0xAE,0xAF,
    0xBC,0xBD,0xBE,0xBF,
    0xCD,0xCE,0xCF,
    0xDE,0xDF,
    0xEF
};

__device__ __forceinline__ float warpSum(float v) {
#pragma unroll
    for (int o = 16; o > 0; o >>= 1) v += __shfl_down_sync(0xffffffffu, v, o);
    return v;
}
__device__ __forceinline__ float ex2a(float x) {
    float r; asm("ex2.approx.f32 %0, %1;" : "=f"(r) : "f"(x)); return r;
}
__device__ __forceinline__ float sqrta(float x) {
    float r; asm("sqrt.approx.f32 %0, %1;" : "=f"(r) : "f"(x)); return r;
}
__device__ __forceinline__ unsigned long long pk2(float a, float b) {
    unsigned long long r; asm("mov.b64 %0, {%1, %2};" : "=l"(r) : "f"(a), "f"(b)); return r;
}
__device__ __forceinline__ void upk2(unsigned long long v, float& a, float& b) {
    asm("mov.b64 {%0, %1}, %2;" : "=f"(a), "=f"(b) : "l"(v));
}
__device__ __forceinline__ unsigned long long mul2(unsigned long long a, unsigned long long b) {
    unsigned long long r; asm("mul.rn.f32x2 %0, %1, %2;" : "=l"(r) : "l"(a), "l"(b)); return r;
}
__device__ __forceinline__ unsigned long long add2(unsigned long long a, unsigned long long b) {
    unsigned long long r; asm("add.rn.f32x2 %0, %1, %2;" : "=l"(r) : "l"(a), "l"(b)); return r;
}
__device__ __forceinline__ void ldsm_x4(unsigned smaddr, unsigned& r0, unsigned& r1,
                                        unsigned& r2, unsigned& r3) {
    asm volatile("ldmatrix.sync.aligned.m8n8.x4.shared.b16 {%0,%1,%2,%3}, [%4];"
                 : "=r"(r0), "=r"(r1), "=r"(r2), "=r"(r3) : "r"(smaddr));
}
__device__ __forceinline__ void mma_bf16(float& c0, float& c1, float& c2, float& c3,
                                         unsigned a0, unsigned a1, unsigned a2, unsigned a3,
                                         unsigned b0, unsigned b1) {
    asm volatile("mma.sync.aligned.m16n8k16.row.col.f32.bf16.bf16.f32 "
                 "{%0,%1,%2,%3}, {%4,%5,%6,%7}, {%8,%9}, {%0,%1,%2,%3};"
                 : "+f"(c0), "+f"(c1), "+f"(c2), "+f"(c3)
                 : "r"(a0), "r"(a1), "r"(a2), "r"(a3), "r"(b0), "r"(b1));
}

// weighted bins-in-lanes accumulate: input is quantized u8 value as float
__device__ __forceinline__ void accumU8(float uf, float wt, float A, float Bc, float umax,
                                        unsigned long long* Hc, unsigned long long C4p) {
    float u = fminf(uf, umax);
    float w0 = wt * ex2a(A * u * u);
    float r0 = ex2a(fmaf(Bc, u, K_O));
    float w1 = w0 * r0;
    float r2 = r0 * r0;
    unsigned long long W = pk2(w0, w1);
    unsigned long long M = pk2(r2 * C_C1, r2 * C_C3);
    Hc[0] = add2(Hc[0], W);
#pragma unroll
    for (int p = 1; p < 8; p++) {
        W = mul2(W, M);
        M = mul2(M, C4p);
        Hc[p] = add2(Hc[p], W);
    }
}

__device__ __forceinline__ float wgt_diag(int el) {
    int lr = (el >> 4) & 15, lc = el & 15;
    return (lc > lr) ? 2.f : ((lc == lr) ? 1.f : 0.f);
}

// ---------------------------------------------------------------------------
// Unified kernel. Blocks 0..255: per-graph-view signature (Gram via mma.sync,
// u8 D in smem, factorized-exp histogram). Blocks 256..271: NT-Xent (16 rows
// each). Atomic-ticket final combine -> out. One wave at 2 CTAs/SM.
// ---------------------------------------------------------------------------
__global__ void __launch_bounds__(512, 2)
kMain(const float* __restrict__ H1, const float* __restrict__ H2,
      const float* __restrict__ z1, const float* __restrict__ z2,
      float* __restrict__ out) {
    extern __shared__ char sm[];
    int tid = threadIdx.x;
    int w = tid >> 5, lane = tid & 31;
    int b = blockIdx.x;

    if (b < 256) {
        // =================== signature role ===================
        __nv_bfloat16* sH = (__nv_bfloat16*)(sm + OFF_H);
        float* sSq   = (float*)(sm + OFF_SQ);
        float* sRed  = (float*)(sm + OFF_RED);
        float* sHist = (float*)(sm + OFF_HIST);
        float* sMisc = (float*)(sm + OFF_MISC);
        const unsigned sHb = (unsigned)__cvta_generic_to_shared(sm) + OFF_H;

        const float* Hg = (b < G) ? (H1 + (size_t)b * NODES * DFEAT)
                                  : (H2 + (size_t)(b - G) * NODES * DFEAT);

        // load H -> bf16 smem (pitched)
        for (int t = tid; t < NODES * (DFEAT / 4); t += 512) {
            int row = t >> 5, c4 = t & 31;
            float4 v = ((const float4*)Hg)[(size_t)row * (DFEAT / 4) + c4];
            __nv_bfloat162 b01 = __floats2bfloat162_rn(v.x, v.y);
            __nv_bfloat162 b23 = __floats2bfloat162_rn(v.z, v.w);
            uint2 u;
            u.x = *(unsigned*)&b01;
            u.y = *(unsigned*)&b23;
            *(uint2*)(sm + OFF_H + (row * PH + c4 * 4) * 2) = u;
        }
        __syncthreads();

        // row norms (bf16 source)
        float myS = 0.f;
        if (tid < NODES) {
            const __nv_bfloat162* r = (const __nv_bfloat162*)(sH + tid * PH);
#pragma unroll 8
            for (int k = 0; k < DFEAT / 2; k++) {
                float2 f = __bfloat1622float2(r[k]);
                myS = fmaf(f.x, f.x, myS);
                myS = fmaf(f.y, f.y, myS);
            }
            sSq[tid] = myS;
        }
        // reduce mean(sq) -> quantization scale qs
        {
            float v = (tid < NODES) ? myS : 0.f;
            v = warpSum(v);
            if (lane == 0 && w < 8) sRed[w] = v;
        }
        __syncthreads();
        if (tid == 0) {
            float msq = 0.f;
#pragma unroll
            for (int i = 0; i < 8; i++) msq += sRed[i];
            msq *= (1.0f / 256.0f);
            float d_est = sqrtf(2.0f * msq) + 1e-12f;
            sMisc[1] = 255.0f / (2.75f * d_est);     // qs
        }
        __syncthreads();
        float qs = sMisc[1];

        // Gram over upper-triangle tiles; warp w handles slots w, w+16, ...
        int lrow = lane & 15;
        int lcol8 = (lane >> 4) << 3;
        int gq = lane >> 2;
        int tq = lane & 3;
        float dsum = 0.f;

        for (int s = w; s < 136; s += 16) {
            int tt = c_slot[s];
            int i0 = (tt >> 4) * 16, j0 = (tt & 15) * 16;
            bool isDiag = (s < 16);

            float c0[4] = {0.f, 0.f, 0.f, 0.f};
            float c1[4] = {0.f, 0.f, 0.f, 0.f};
#pragma unroll
            for (int kc = 0; kc < 8; kc++) {
                unsigned a0, a1, a2, a3, b0, b1, b2, b3;
                unsigned ad = sHb + 2u * ((i0 + lrow) * PH + kc * 16 + lcol8);
                ldsm_x4(ad, a0, a1, a2, a3);
                unsigned bd = sHb + 2u * ((j0 + lrow) * PH + kc * 16 + lcol8);
                ldsm_x4(bd, b0, b1, b2, b3);
                mma_bf16(c0[0], c0[1], c0[2], c0[3], a0, a1, a2, a3, b0, b2);
                mma_bf16(c1[0], c1[1], c1[2], c1[3], a0, a1, a2, a3, b1, b3);
            }
#pragma unroll
            for (int t2 = 0; t2 < 2; t2++) {
                const float* cc = t2 ? c1 : c0;
                int lc = t2 * 8 + 2 * tq;
                int jc = j0 + lc;
                float sqj0 = sSq[jc], sqj1 = sSq[jc + 1];
#pragma unroll
                for (int rh = 0; rh < 2; rh++) {
                    int lr = gq + rh * 8;
                    int r = i0 + lr;
                    float sqi = sSq[r];
                    float da = sqrta(fmaxf(fmaf(-2.f, cc[rh * 2 + 0], sqi + sqj0), 0.f) + 1e-12f);
                    float db = sqrta(fmaxf(fmaf(-2.f, cc[rh * 2 + 1], sqi + sqj1), 0.f) + 1e-12f);
                    if (!isDiag) {
                        dsum += 2.f * (da + db);
                    } else {
                        float wa = (lc > lr) ? 2.f : ((lc == lr) ? 1.f : 0.f);
                        float wb = (lc + 1 > lr) ? 2.f : ((lc + 1 == lr) ? 1.f : 0.f);
                        dsum = fmaf(wa, da, dsum);
                        dsum = fmaf(wb, db, dsum);
                    }
                    unsigned ua = __float2uint_rn(fminf(da * qs, 255.f));
                    unsigned ub = __float2uint_rn(fminf(db * qs, 255.f));
                    *(unsigned short*)(sm + OFF_D + s * 256 + lr * 16 + lc) =
                        (unsigned short)(ua | (ub << 8));
                }
            }
        }

        dsum = warpSum(dsum);
        if (lane == 0) sRed[w] = dsum;
        __syncthreads();
        if (tid == 0) {
            float tot = 0.f;
#pragma unroll
            for (int i = 0; i < 16; i++) tot += sRed[i];
            float mean = tot * (1.0f / 65536.0f);
            float invm = 1.0f / (mean + 1e-8f);
            float cq = invm / qs;                 // x = u * cq
            sMisc[2] = K_W * cq * cq;             // A
            sMisc[3] = K_L * cq;                  // Bc
            sMisc[4] = 2.46f / cq;                // umax
        }
        __syncthreads();
        float A = sMisc[2], Bc = sMisc[3], umax = sMisc[4];

        // histogram: thread t owns bytes [t*68, t*68+68) of the 34816-B D pack
        unsigned long long HA[8], HB[8];
#pragma unroll
        for (int p = 0; p < 8; p++) { HA[p] = pk2(0.f, 0.f); HB[p] = pk2(0.f, 0.f); }
        const unsigned long long C4p = pk2(C_C4, C_C4);

        {
            int baseEl = tid * 68;
            const unsigned* Dp = (const unsigned*)(sm + OFF_D + baseEl);
            if (baseEl >= 4096) {
#pragma unroll 4
                for (int it = 0; it < 17; it++) {
                    unsigned v = Dp[it];
                    accumU8((float)(v & 0xffu),         2.f, A, Bc, umax, HA, C4p);
                    accumU8((float)((v >> 8) & 0xffu),  2.f, A, Bc, umax, HB, C4p);
                    accumU8((float)((v >> 16) & 0xffu), 2.f, A, Bc, umax, HA, C4p);
                    accumU8((float)(v >> 24),           2.f, A, Bc, umax, HB, C4p);
                }
            } else {
#pragma unroll 4
                for (int it = 0; it < 17; it++) {
                    unsigned v = Dp[it];
                    int e = baseEl + it * 4;
                    float w0 = (e + 0 >= 4096) ? 2.f : wgt_diag(e + 0);
                    float w1 = (e + 1 >= 4096) ? 2.f : wgt_diag(e + 1);
                    float w2 = (e + 2 >= 4096) ? 2.f : wgt_diag(e + 2);
                    float w3 = (e + 3 >= 4096) ? 2.f : wgt_diag(e + 3);
                    accumU8((float)(v & 0xffu),         w0, A, Bc, umax, HA, C4p);
                    accumU8((float)((v >> 8) & 0xffu),  w1, A, Bc, umax, HB, C4p);
                    accumU8((float)((v >> 16) & 0xffu), w2, A, Bc, umax, HA, C4p);
                    accumU8((float)(v >> 24),           w3, A, Bc, umax, HB, C4p);
                }
            }
        }

        float hl[16];
#pragma unroll
        for (int p = 0; p < 8; p++) {
            float a0, a1, b0, b1;
            upk2(HA[p], a0, a1);
            upk2(HB[p], b0, b1);
            hl[2 * p] = a0 + b0;
            hl[2 * p + 1] = a1 + b1;
        }
#pragma unroll
        for (int k = 0; k < 16; k++) {
            float v = warpSum(hl[k]);
            if (lane == 0) sHist[w * 16 + k] = v;
        }
        __syncthreads();
        if (tid < 16) {
            float s = 0.f;
#pragma unroll
            for (int ww = 0; ww < 16; ww++) s += sHist[ww * 16 + tid];
            sHist[tid] = s;      // reuse slots 0..15 for column sums (post-sync safe)
        }
        __syncthreads();
        if (tid == 0) {
            float S = 0.f;
#pragma unroll
            for (int k = 0; k < 16; k++) S += sHist[k];
            sMisc[0] = 1.0f / (S + 1e-8f);
        }
        __syncthreads();
        if (tid < 16) g_sig[b * KB + tid] = sHist[tid] * sMisc[0];

    } else {
        // =================== NT-Xent role (16 blocks x 16 rows) ===================
        int c = b - 256;
        unsigned* zw = (unsigned*)sm;                       // 256 * PZW u32
        float* sRedC = (float*)(sm + 256 * PZW * 4);        // 16 floats

        if (tid < 256) {
            const float* zr = (tid < G) ? (z1 + tid * DFEAT) : (z2 + (tid - G) * DFEAT);
            float ssum = 0.f;
#pragma unroll 8
            for (int k = 0; k < DFEAT; k += 4) {
                float4 v = *(const float4*)(zr + k);
                ssum = fmaf(v.x, v.x, ssum);
                ssum = fmaf(v.y, v.y, ssum);
                ssum = fmaf(v.z, v.z, ssum);
                ssum = fmaf(v.w, v.w, ssum);
            }
            float inv = 1.0f / (sqrtf(ssum) + 1e-8f);
#pragma unroll 8
            for (int k = 0; k < DFEAT; k += 2) {
                __nv_bfloat162 bb = __floats2bfloat162_rn(zr[k] * inv, zr[k + 1] * inv);
                zw[tid * PZW + (k >> 1)] = *(unsigned*)&bb;
            }
        }
        __syncthreads();

        int i = c * 16 + w;
        int label = (i < G) ? i + G : i - G;
        float acc[8];
#pragma unroll
        for (int s2 = 0; s2 < 8; s2++) acc[s2] = 0.f;

        for (int k = 0; k < 64; k++) {
            unsigned zi = zw[i * PZW + k];
            float a0 = __uint_as_float(zi << 16);
            float a1 = __uint_as_float(zi & 0xffff0000u);
#pragma unroll
            for (int s2 = 0; s2 < 8; s2++) {
                unsigned zj = zw[(lane + 32 * s2) * PZW + k];
                float b0 = __uint_as_float(zj << 16);
                float b1 = __uint_as_float(zj & 0xffff0000u);
                acc[s2] = fmaf(a0, b0, acc[s2]);
                acc[s2] = fmaf(a1, b1, acc[s2]);
            }
        }

        float m = -1e30f, slab = 0.f;
        float sims[8];
#pragma unroll
        for (int s2 = 0; s2 < 8; s2++) {
            int j = lane + 32 * s2;
            float sim = acc[s2] * 2.0f;          // 1/TEMP
            if (j == i) sim = -1e9f;
            sims[s2] = sim;
            m = fmaxf(m, sim);
            if (j == label) slab = sim;
        }
#pragma unroll
        for (int o = 16; o > 0; o >>= 1)
            m = fmaxf(m, __shfl_xor_sync(0xffffffffu, m, o));
        float se = 0.f;
#pragma unroll
        for (int s2 = 0; s2 < 8; s2++) se += __expf(sims[s2] - m);
        se = warpSum(se);
        slab = warpSum(slab);
        if (lane == 0) sRedC[w] = (m + logf(se)) - slab;
        __syncthreads();
        if (tid == 0) {
            float t = 0.f;
#pragma unroll
            for (int s2 = 0; s2 < 16; s2++) t += sRedC[s2];
            g_ntx[c] = t;
        }
    }

    // =================== ticket: last block combines ===================
    __threadfence();
    __shared__ int sLast;
    __shared__ float sR2[4];
    if (tid == 0) sLast = (atomicAdd(&g_cnt, 1) == 271) ? 1 : 0;
    __syncthreads();
    if (sLast) {
        if (tid == 0) g_cnt = 0;     // reset for graph replay
        __threadfence();
        float t2 = 0.f;
        if (tid < 128) {
            const float* a = g_sig + tid * KB;
            const float* bb = g_sig + (G + tid) * KB;
#pragma unroll
            for (int k = 0; k < KB; k++) {
                float d = a[k] - bb[k];
                t2 += d * d;
            }
            t2 *= (1.0f / KB);
        }
        t2 = warpSum(t2);
        if (lane == 0 && w < 4) sR2[w] = t2;
        __syncthreads();
        float ntx = 0.f;
        if (tid < 32) {
            ntx = (tid < 16) ? g_ntx[tid] : 0.f;
            ntx = warpSum(ntx);
        }
        if (tid == 0) {
            float topo = (sR2[0] + sR2[1] + sR2[2] + sR2[3]) * (1.0f / G);
            out[0] = 0.1f * (topo + ntx * (1.0f / 256.0f));
        }
    }
}

// ---------------------------------------------------------------------------
extern "C" void kernel_launch(void* const* d_in, const int* in_sizes, int n_in,
                              void* d_out, int out_size) {
    const float* H1 = (const float*)d_in[0];
    const float* H2 = (const float*)d_in[2];
    const float* z1 = (const float*)d_in[4];
    const float* z2 = (const float*)d_in[5];

    cudaFuncSetAttribute(kMain, cudaFuncAttributeMaxDynamicSharedMemorySize, SMEM_T);
    cudaFuncSetAttribute(kMain, cudaFuncAttributePreferredSharedMemoryCarveout,
                         cudaSharedmemCarveoutMaxShared);

    kMain<<<272, 512, SMEM_T>>>(H1, H2, z1, z2, (float*)d_out);
}